// round 6
// baseline (speedup 1.0000x reference)
#include <cuda_runtime.h>
#include <cstdint>
#include <cmath>

typedef unsigned long long u64;

#define NT 448                  // 14 warps per CTA, 1 CTA/SM, grid=147
#define PM 2344                 // floats per muscle block in smem
#define OFF_W1T 0               // 3*32 transposed [i][o]
#define OFF_B1P 96              // 32
#define OFF_W2  128             // 32*32 NATIVE [o][i]
#define OFF_B2Z 1152            // 64  ({b_o, 0} interleaved)
#define OFF_W3  1216            // 32*32 NATIVE [o][i]
#define OFF_B3Z 2240            // 64
#define OFF_W4  2304            // 32 native [i]
#define OFF_B4  2336            // 1
#define OFF_PAR 2337            // 7: K0,K1,L0,L1,Ms,Ms2,K1L1
#define SMEM_BYTES (8*PM*4)
#define DTC 0.0166667f
#define NNR 0.3f

// ---------- packed f32x2 helpers ----------
__device__ __forceinline__ u64 fma2(u64 a, u64 b, u64 c) {
    u64 d; asm("fma.rn.f32x2 %0, %1, %2, %3;" : "=l"(d) : "l"(a), "l"(b), "l"(c)); return d;
}
__device__ __forceinline__ u64 add2(u64 a, u64 b) {
    u64 d; asm("add.rn.f32x2 %0, %1, %2;" : "=l"(d) : "l"(a), "l"(b)); return d;
}
__device__ __forceinline__ u64 mul2(u64 a, u64 b) {
    u64 d; asm("mul.rn.f32x2 %0, %1, %2;" : "=l"(d) : "l"(a), "l"(b)); return d;
}
__device__ __forceinline__ u64 pack2(float lo, float hi) {
    u64 r; asm("mov.b64 %0, {%1, %2};" : "=l"(r) : "r"(__float_as_uint(lo)), "r"(__float_as_uint(hi))); return r;
}
__device__ __forceinline__ void unpack2(u64 v, float& lo, float& hi) {
    unsigned a, b; asm("mov.b64 {%0, %1}, %2;" : "=r"(a), "=r"(b) : "l"(v));
    lo = __uint_as_float(a); hi = __uint_as_float(b);
}
__device__ __forceinline__ float tanh_ap(float x) {
    float y; asm("tanh.approx.f32 %0, %1;" : "=f"(y) : "f"(x)); return y;
}
__device__ __forceinline__ u64 leaky2(u64 x, u64 c505, u64 c495) {
    u64 ax = x & 0x7FFFFFFF7FFFFFFFull;
    return fma2(x, c505, mul2(ax, c495));
}
__device__ __forceinline__ float leakys(float x) {
    return fmaf(0.505f, x, 0.495f * fabsf(x));
}

// closed-form 2x2 expm + phi1 solve (validated: rel_err 5.7e-7)
__device__ __forceinline__ void finalize(float Ks, float Bs, float s0, float s1,
                                         float Iv, float invI, float Bv, float Kv,
                                         float& o0, float& o1) {
    float A10 = -(Ks + Kv) * invI;
    float Dd  = 2.0f * sqrtf(fmaxf(Ks * Iv, 0.0f));
    float A11 = -(Dd + Bv) * invI;
    float B10 = Bs * invI;
    float a10 = A10 * DTC, a11 = A11 * DTC;
    float s = 0.5f * a11;
    float q = fmaf(s, s, DTC * a10);
    float c, kf;
    if (q >= 0.0f) {
        float w = sqrtf(q);
        c = coshf(w);
        kf = (w > 1e-4f) ? sinhf(w) / w : 1.0f + q * (1.0f / 6.0f);
    } else {
        float w = sqrtf(-q);
        c = __cosf(w);
        kf = (w > 1e-4f) ? __sinf(w) / w : 1.0f + q * (1.0f / 6.0f);
    }
    float es = __expf(s);
    float g  = es * fmaf(-s, kf, c);
    float kk = es * kf;
    float Ad01 = kk * DTC;
    float Ad10 = kk * a10;
    float Ad11 = g + kk * a11;
    float v  = DTC * B10;
    float y1 = kk * v;
    float r1 = (Ad11 - 1.0f) * v;
    float y0 = (r1 - a11 * y1) / a10;
    o0 = fmaf(g,    s0, fmaf(Ad01, s1, y0));
    o1 = fmaf(Ad10, s0, fmaf(Ad11, s1, y1));
}

__global__ __launch_bounds__(NT, 1)
void joint_kernel(const float* __restrict__ SS,  const float* __restrict__ AL,
                  const float* __restrict__ K0,  const float* __restrict__ K1,
                  const float* __restrict__ L0,  const float* __restrict__ L1,
                  const float* __restrict__ Ms,  const float* __restrict__ Ip,
                  const float* __restrict__ Bvp, const float* __restrict__ Kvp,
                  const float* __restrict__ W1,  const float* __restrict__ b1,
                  const float* __restrict__ W2,  const float* __restrict__ b2,
                  const float* __restrict__ W3,  const float* __restrict__ b3,
                  const float* __restrict__ W4,  const float* __restrict__ b4,
                  float* __restrict__ out, int B) {
    extern __shared__ float sm[];
    const int tid = threadIdx.x;

    // ---- smem tables ----
    for (int t = tid; t < 768; t += NT) {            // W1[m][o][i] -> [m][i][o]
        int m = t / 96, r = t - m * 96, o = r / 3, i = r - o * 3;
        sm[m * PM + OFF_W1T + i * 32 + o] = W1[t];
    }
    for (int t = tid; t < 256; t += NT) {            // b1 native
        int m = t >> 5, o = t & 31;
        sm[m * PM + OFF_B1P + o] = b1[t];
    }
    {                                                // W2, W3 native copies (float4)
        const float4* s2 = reinterpret_cast<const float4*>(W2);
        const float4* s3 = reinterpret_cast<const float4*>(W3);
        for (int t = tid; t < 2048; t += NT) {
            int m = t >> 8, r = t & 255;
            *reinterpret_cast<float4*>(&sm[m * PM + OFF_W2 + r * 4]) = s2[t];
            *reinterpret_cast<float4*>(&sm[m * PM + OFF_W3 + r * 4]) = s3[t];
        }
    }
    for (int t = tid; t < 512; t += NT) {            // b2, b3 as {b, 0}
        int m = t >> 6, r = t & 63;
        float v2 = (r & 1) ? 0.0f : b2[m * 32 + (r >> 1)];
        float v3 = (r & 1) ? 0.0f : b3[m * 32 + (r >> 1)];
        sm[m * PM + OFF_B2Z + r] = v2;
        sm[m * PM + OFF_B3Z + r] = v3;
    }
    for (int t = tid; t < 256; t += NT) {            // W4 native
        int m = t >> 5, i = t & 31;
        sm[m * PM + OFF_W4 + i] = W4[t];
    }
    if (tid < 8) {
        int m = tid;
        sm[m * PM + OFF_B4] = b4[m];
        float k0 = K0[m], k1 = K1[m], l0 = L0[m], l1 = L1[m], ms = Ms[m];
        float* p = sm + m * PM + OFF_PAR;
        p[0] = k0; p[1] = k1; p[2] = l0; p[3] = l1;
        p[4] = ms; p[5] = ms * ms; p[6] = k1 * l1;
    }
    __syncthreads();

    // ---- one element per thread ----
    int e = blockIdx.x * NT + tid;
    if (e >= B) e = B - 1;                // clamp: duplicate work, benign

    const u64 c505 = pack2(0.505f, 0.505f);
    const u64 c495 = pack2(0.495f, 0.495f);

    const float2 ssA = reinterpret_cast<const float2*>(SS)[e];

    // preload all 8 activations a[m] (two float4 loads, 32B-aligned)
    float av[8];
    {
        const float4* ap = reinterpret_cast<const float4*>(AL + (size_t)e * 8);
        float4 a0 = ap[0], a1 = ap[1];
        av[0] = a0.x; av[1] = a0.y; av[2] = a0.z; av[3] = a0.w;
        av[4] = a1.x; av[5] = a1.y; av[6] = a1.z; av[7] = a1.w;
#pragma unroll
        for (int m = 0; m < 8; m++) av[m] = fminf(fmaxf(av[m], 0.0f), 1.0f);
    }

    float Ksum = 0.f, Bsum = 0.f;

#pragma unroll 1
    for (int m = 0; m < 8; m++) {
        const float* mb = sm + m * PM;
        const float Msv = mb[OFF_PAR + 4];

        const float a = av[m];
        const float lv = ssA.x * Msv;

        // ---- layer 1 (3 -> 32): hp[p] = {h_2p, h_2p+1} ----
        u64 hp[16];
        {
            u64 xl = pack2(lv, lv);
            u64 xd = pack2(ssA.y * Msv, ssA.y * Msv);
            u64 xa = pack2(a, a);
            const u64* b1p = reinterpret_cast<const u64*>(mb + OFF_B1P);
            const u64* w0r = reinterpret_cast<const u64*>(mb + OFF_W1T);
            const u64* w1r = reinterpret_cast<const u64*>(mb + OFF_W1T + 32);
            const u64* w2r = reinterpret_cast<const u64*>(mb + OFF_W1T + 64);
#pragma unroll
            for (int pp = 0; pp < 16; pp++) {
                u64 acc = fma2(xl, w0r[pp], b1p[pp]);
                acc = fma2(xd, w1r[pp], acc);
                acc = fma2(xa, w2r[pp], acc);
                hp[pp] = leaky2(acc, c505, c495);
            }
        }

        // ---- layers 2 & 3 (32 -> 32), parity-split accumulation ----
#pragma unroll 1
        for (int L = 0; L < 2; L++) {
            const float* W  = mb + (L ? OFF_W3 : OFF_W2);
            const u64*  BZ  = reinterpret_cast<const u64*>(mb + (L ? OFF_B3Z : OFF_B2Z));
            u64 hn[16];
#pragma unroll
            for (int og = 0; og < 8; og++) {                 // 4 output rows per group
                const float* wr = W + og * 128;
                u64 acc0 = BZ[og * 4 + 0];
                u64 acc1 = BZ[og * 4 + 1];
                u64 acc2 = BZ[og * 4 + 2];
                u64 acc3 = BZ[og * 4 + 3];
#pragma unroll
                for (int ip = 0; ip < 16; ip += 2) {
                    ulonglong2 w0 = *reinterpret_cast<const ulonglong2*>(wr +  0 + ip * 2);
                    ulonglong2 w1 = *reinterpret_cast<const ulonglong2*>(wr + 32 + ip * 2);
                    ulonglong2 w2 = *reinterpret_cast<const ulonglong2*>(wr + 64 + ip * 2);
                    ulonglong2 w3 = *reinterpret_cast<const ulonglong2*>(wr + 96 + ip * 2);
                    acc0 = fma2(hp[ip], w0.x, acc0);
                    acc1 = fma2(hp[ip], w1.x, acc1);
                    acc2 = fma2(hp[ip], w2.x, acc2);
                    acc3 = fma2(hp[ip], w3.x, acc3);
                    acc0 = fma2(hp[ip+1], w0.y, acc0);
                    acc1 = fma2(hp[ip+1], w1.y, acc1);
                    acc2 = fma2(hp[ip+1], w2.y, acc2);
                    acc3 = fma2(hp[ip+1], w3.y, acc3);
                }
                float x0, y0, x1, y1;
                unpack2(acc0, x0, y0);
                unpack2(acc1, x1, y1);
                hn[og*2]   = pack2(leakys(x0 + y0), leakys(x1 + y1));
                unpack2(acc2, x0, y0);
                unpack2(acc3, x1, y1);
                hn[og*2+1] = pack2(leakys(x0 + y0), leakys(x1 + y1));
            }
#pragma unroll
            for (int pp = 0; pp < 16; pp++) hp[pp] = hn[pp];
        }

        // ---- layer 4 (32 -> 1) + tanh ----
        const u64* w4p = reinterpret_cast<const u64*>(mb + OFF_W4);
        const float b4v = mb[OFF_B4];
        float nn;
        {
            u64 sA = 0ull, sB = 0ull;
#pragma unroll
            for (int ip = 0; ip < 16; ip += 2) {
                sA = fma2(hp[ip],   w4p[ip],   sA);
                sB = fma2(hp[ip+1], w4p[ip+1], sB);
            }
            u64 s = add2(sA, sB);
            float lo, hi; unpack2(s, lo, hi);
            nn = NNR * tanh_ap(lo + hi + b4v);
        }

        // ---- muscle epilogue (par scalars loaded late) ----
        const float K0v = mb[OFF_PAR + 0], K1v = mb[OFF_PAR + 1];
        const float L0v = mb[OFF_PAR + 2], L1v = mb[OFF_PAR + 3];
        const float Ms2v = mb[OFF_PAR + 5], K1L1v = mb[OFF_PAR + 6];
        float K = fmaf(a, K1v, K0v);
        Ksum = fmaf(K, Ms2v, Ksum);
        float tL = fmaf(a, L1v, L0v) - fabsf(lv);
        float BF = fmaf(a * a * nn, K1L1v, K * tL);
        Bsum = fmaf(BF, Msv, Bsum);
    }

    // ---- expm epilogue + stores ----
    const float Iv = __ldg(Ip), Bv = __ldg(Bvp), Kv = __ldg(Kvp);
    const float invI = 1.0f / Iv;

    float o0, o1;
    finalize(Ksum, Bsum, ssA.x, ssA.y, Iv, invI, Bv, Kv, o0, o1);
    out[e] = o0;
    reinterpret_cast<float2*>(out + B)[e] = make_float2(o0, o1);
}

extern "C" void kernel_launch(void* const* d_in, const int* in_sizes, int n_in,
                              void* d_out, int out_size) {
    const float* SS  = (const float*)d_in[0];
    const float* AL  = (const float*)d_in[1];
    const float* K0  = (const float*)d_in[2];
    const float* K1  = (const float*)d_in[3];
    const float* L0  = (const float*)d_in[4];
    const float* L1  = (const float*)d_in[5];
    const float* Ms  = (const float*)d_in[6];
    const float* Ip  = (const float*)d_in[7];
    const float* Bv  = (const float*)d_in[8];
    const float* Kv  = (const float*)d_in[9];
    const float* W1  = (const float*)d_in[10];
    const float* b1  = (const float*)d_in[11];
    const float* W2  = (const float*)d_in[12];
    const float* b2  = (const float*)d_in[13];
    const float* W3  = (const float*)d_in[14];
    const float* b3  = (const float*)d_in[15];
    const float* W4  = (const float*)d_in[16];
    const float* b4  = (const float*)d_in[17];
    float* out = (float*)d_out;

    const int B = in_sizes[0] / 2;
    const int grid = (B + NT - 1) / NT;

    cudaFuncSetAttribute(joint_kernel, cudaFuncAttributeMaxDynamicSharedMemorySize, SMEM_BYTES);
    joint_kernel<<<grid, NT, SMEM_BYTES>>>(SS, AL, K0, K1, L0, L1, Ms, Ip, Bv, Kv,
                                           W1, b1, W2, b2, W3, b3, W4, b4, out, B);
}

// round 8
// speedup vs baseline: 2.5692x; 2.5692x over previous
#include <cuda_runtime.h>
#include <cuda_bf16.h>
#include <cstdint>
#include <cmath>

#define NT 512                 // 16 warps per CTA
#define DTC 0.0166667f
#define NNR 0.3f

// ---- smem layout (u32 units) ----
// WB: bf16x2 entries, idx = ((((m*3+l)*2+ks)*2+kh)*32+o)*4+tig  -> 12288 u32
#define WB_O   0
#define BS_O   12288           // fp32 [m][3][32] biases b1,b2,b3 (768)
#define W4_O   13056           // fp32 [m][32]
#define B4_O   13312           // fp32 [8]
#define PAR_O  13320           // fp32 [8][8]
#define SMEM_U 13384
#define SMEM_BYTES (SMEM_U*4)

__device__ __forceinline__ int widx(int m, int l, int ks, int kh, int o, int tig) {
    return ((((m * 3 + l) * 2 + ks) * 2 + kh) * 32 + o) * 4 + tig;
}

// pack {lo=a, hi=b} as bf16x2
#define CVT_BF16X2(res, a, b) \
    asm("cvt.rn.bf16x2.f32 %0, %1, %2;" : "=r"(res) : "f"(b), "f"(a))

__device__ __forceinline__ void mma16816(float* d, const uint32_t* a, uint32_t b0, uint32_t b1) {
    asm volatile("mma.sync.aligned.m16n8k16.row.col.f32.bf16.bf16.f32 "
                 "{%0,%1,%2,%3}, {%4,%5,%6,%7}, {%8,%9}, {%0,%1,%2,%3};"
                 : "+f"(d[0]), "+f"(d[1]), "+f"(d[2]), "+f"(d[3])
                 : "r"(a[0]), "r"(a[1]), "r"(a[2]), "r"(a[3]), "r"(b0), "r"(b1));
}

__device__ __forceinline__ float tanh_ap(float x) {
    float y; asm("tanh.approx.f32 %0, %1;" : "=f"(y) : "f"(x)); return y;
}
__device__ __forceinline__ float leakys(float x) {
    return fmaf(0.505f, x, 0.495f * fabsf(x));
}

// closed-form 2x2 expm + phi1 solve (validated R1-R6: rel_err 5.7e-7)
__device__ __forceinline__ void finalize(float Ks, float Bs, float s0, float s1,
                                         float Iv, float invI, float Bv, float Kv,
                                         float& o0, float& o1) {
    float A10 = -(Ks + Kv) * invI;
    float Dd  = 2.0f * sqrtf(fmaxf(Ks * Iv, 0.0f));
    float A11 = -(Dd + Bv) * invI;
    float B10 = Bs * invI;
    float a10 = A10 * DTC, a11 = A11 * DTC;
    float s = 0.5f * a11;
    float q = fmaf(s, s, DTC * a10);
    float c, kf;
    if (q >= 0.0f) {
        float w = sqrtf(q);
        c = coshf(w);
        kf = (w > 1e-4f) ? sinhf(w) / w : 1.0f + q * (1.0f / 6.0f);
    } else {
        float w = sqrtf(-q);
        c = __cosf(w);
        kf = (w > 1e-4f) ? __sinf(w) / w : 1.0f + q * (1.0f / 6.0f);
    }
    float es = __expf(s);
    float g  = es * fmaf(-s, kf, c);
    float kk = es * kf;
    float Ad01 = kk * DTC;
    float Ad10 = kk * a10;
    float Ad11 = g + kk * a11;
    float v  = DTC * B10;
    float y1 = kk * v;
    float r1 = (Ad11 - 1.0f) * v;
    float y0 = (r1 - a11 * y1) / a10;
    o0 = fmaf(g,    s0, fmaf(Ad01, s1, y0));
    o1 = fmaf(Ad10, s0, fmaf(Ad11, s1, y1));
}

__global__ __launch_bounds__(NT, 1)
void joint_mma(const float* __restrict__ SS,  const float* __restrict__ AL,
               const float* __restrict__ K0,  const float* __restrict__ K1,
               const float* __restrict__ L0,  const float* __restrict__ L1,
               const float* __restrict__ Ms,  const float* __restrict__ Ip,
               const float* __restrict__ Bvp, const float* __restrict__ Kvp,
               const float* __restrict__ W1,  const float* __restrict__ b1,
               const float* __restrict__ W2,  const float* __restrict__ b2,
               const float* __restrict__ W3,  const float* __restrict__ b3,
               const float* __restrict__ W4,  const float* __restrict__ b4,
               float* __restrict__ out, int B) {
    extern __shared__ uint32_t smu[];
    float* smf = reinterpret_cast<float*>(smu);
    const int tid = threadIdx.x;

    // ---- stage weight fragments (bf16x2, mma B-fragment order) ----
    for (int t = tid; t < 12288; t += NT) {
        int m  = t / 1536;  int r = t - m * 1536;
        int l  = r / 512;   r -= l * 512;
        int ks = r / 256;   r -= ks * 256;
        int kh = r / 128;   r -= kh * 128;
        int o  = r >> 2;    int tg = r & 3;
        int i0 = ks * 16 + kh * 8 + tg * 2;
        float v0 = 0.0f, v1 = 0.0f;
        if (l == 0) {
            if (i0 < 3)     v0 = W1[(m * 32 + o) * 3 + i0];
            if (i0 + 1 < 3) v1 = W1[(m * 32 + o) * 3 + i0 + 1];
        } else {
            const float* W = (l == 1) ? W2 : W3;
            v0 = W[(m * 32 + o) * 32 + i0];
            v1 = W[(m * 32 + o) * 32 + i0 + 1];
        }
        uint32_t pk; CVT_BF16X2(pk, v0, v1);
        smu[WB_O + t] = pk;
    }
    for (int t = tid; t < 768; t += NT) {           // biases [m][l][o]
        int m = t / 96, r = t - m * 96, li = r / 32, o = r & 31;
        const float* bp = (li == 0) ? b1 : (li == 1) ? b2 : b3;
        smf[BS_O + t] = bp[m * 32 + o];
    }
    for (int t = tid; t < 256; t += NT) smf[W4_O + t] = W4[t];
    if (tid < 8) {
        smf[B4_O + tid] = b4[tid];
        float ms = Ms[tid];
        float* p = smf + PAR_O + tid * 8;
        p[0] = K0[tid]; p[1] = K1[tid]; p[2] = L0[tid]; p[3] = L1[tid];
        p[4] = ms; p[5] = ms * ms; p[6] = K1[tid] * L1[tid];
    }
    __syncthreads();

    const int lane = tid & 31, wid = tid >> 5;
    const int g = lane >> 2, tig = lane & 3;
    const int cb = 2 * tig;
    const float Iv = __ldg(Ip), Bv = __ldg(Bvp), Kv = __ldg(Kvp);
    const float invI = 1.0f / Iv;
    const float2* SS2 = reinterpret_cast<const float2*>(SS);
    float2* seg2 = reinterpret_cast<float2*>(out + B);

#pragma unroll 1
    for (int c = 0; c < 2; c++) {
        const int chunk = (blockIdx.x * 16 + wid) * 2 + c;
        const int E = chunk * 16;
        int e0 = E + g;     if (e0 >= B) e0 = B - 1;
        int e1 = E + g + 8; if (e1 >= B) e1 = B - 1;
        const float2 ss0 = SS2[e0];
        const float2 ss1 = SS2[e1];
        float Ks0 = 0.f, Bs0 = 0.f, Ks1 = 0.f, Bs1 = 0.f;

#pragma unroll 1
        for (int m = 0; m < 8; m++) {
            const float* par = smf + PAR_O + m * 8;
            const float Msv = par[4];
            float a0v = fminf(fmaxf(__ldg(&AL[(size_t)e0 * 8 + m]), 0.0f), 1.0f);
            float a1v = fminf(fmaxf(__ldg(&AL[(size_t)e1 * 8 + m]), 0.0f), 1.0f);
            const float l0 = ss0.x * Msv, dl0 = ss0.y * Msv;
            const float l1 = ss1.x * Msv, dl1 = ss1.y * Msv;

            // ---- layer-1 A fragment: x = [l, dl, a, 0, ...] (K=16 padded) ----
            uint32_t A0[4];
            {
                uint32_t r0 = 0, r1 = 0;
                if (tig == 0) { CVT_BF16X2(r0, l0, dl0); CVT_BF16X2(r1, l1, dl1); }
                else if (tig == 1) { CVT_BF16X2(r0, a0v, 0.0f); CVT_BF16X2(r1, a1v, 0.0f); }
                A0[0] = r0; A0[1] = r1; A0[2] = 0u; A0[3] = 0u;
            }

            // ---- layer 1 mma (K=16, one step) ----
            float D[4][4];
#pragma unroll
            for (int t4 = 0; t4 < 4; t4++) {
#pragma unroll
                for (int i = 0; i < 4; i++) D[t4][i] = 0.0f;
                uint32_t bb0 = smu[WB_O + widx(m, 0, 0, 0, t4 * 8 + g, tig)];
                uint32_t bb1 = smu[WB_O + widx(m, 0, 0, 1, t4 * 8 + g, tig)];
                mma16816(D[t4], A0, bb0, bb1);
            }

            // ---- layers 2,3: bias+leaky -> A frags -> 2-step K=32 mma ----
#pragma unroll 1
            for (int l = 1; l <= 2; l++) {
                uint32_t Ak0[4], Ak1[4];
                const float* bb = smf + BS_O + (m * 3 + (l - 1)) * 32 + cb;
#pragma unroll
                for (int t4 = 0; t4 < 4; t4++) {
                    float2 bp = *reinterpret_cast<const float2*>(bb + t4 * 8);
                    float h0 = leakys(D[t4][0] + bp.x);
                    float h1 = leakys(D[t4][1] + bp.y);
                    float h2 = leakys(D[t4][2] + bp.x);
                    float h3 = leakys(D[t4][3] + bp.y);
                    uint32_t r01, r23;
                    CVT_BF16X2(r01, h0, h1);
                    CVT_BF16X2(r23, h2, h3);
                    if      (t4 == 0) { Ak0[0] = r01; Ak0[1] = r23; }
                    else if (t4 == 1) { Ak0[2] = r01; Ak0[3] = r23; }
                    else if (t4 == 2) { Ak1[0] = r01; Ak1[1] = r23; }
                    else              { Ak1[2] = r01; Ak1[3] = r23; }
                }
#pragma unroll
                for (int t4 = 0; t4 < 4; t4++) {
#pragma unroll
                    for (int i = 0; i < 4; i++) D[t4][i] = 0.0f;
                    uint32_t bb0 = smu[WB_O + widx(m, l, 0, 0, t4 * 8 + g, tig)];
                    uint32_t bb1 = smu[WB_O + widx(m, l, 0, 1, t4 * 8 + g, tig)];
                    mma16816(D[t4], Ak0, bb0, bb1);
                    bb0 = smu[WB_O + widx(m, l, 1, 0, t4 * 8 + g, tig)];
                    bb1 = smu[WB_O + widx(m, l, 1, 1, t4 * 8 + g, tig)];
                    mma16816(D[t4], Ak1, bb0, bb1);
                }
            }

            // ---- layer 4 (32->1): quad-local dot + reduce ----
            float s0 = 0.f, s1 = 0.f;
            {
                const float* bb = smf + BS_O + (m * 3 + 2) * 32 + cb;
                const float* w4 = smf + W4_O + m * 32 + cb;
#pragma unroll
                for (int t4 = 0; t4 < 4; t4++) {
                    float2 bp = *reinterpret_cast<const float2*>(bb + t4 * 8);
                    float2 wp = *reinterpret_cast<const float2*>(w4 + t4 * 8);
                    s0 = fmaf(leakys(D[t4][0] + bp.x), wp.x, s0);
                    s0 = fmaf(leakys(D[t4][1] + bp.y), wp.y, s0);
                    s1 = fmaf(leakys(D[t4][2] + bp.x), wp.x, s1);
                    s1 = fmaf(leakys(D[t4][3] + bp.y), wp.y, s1);
                }
                s0 += __shfl_xor_sync(0xffffffffu, s0, 1);
                s0 += __shfl_xor_sync(0xffffffffu, s0, 2);
                s1 += __shfl_xor_sync(0xffffffffu, s1, 1);
                s1 += __shfl_xor_sync(0xffffffffu, s1, 2);
            }
            const float b4v = smf[B4_O + m];
            float nn0 = NNR * tanh_ap(s0 + b4v);
            float nn1 = NNR * tanh_ap(s1 + b4v);

            // ---- muscle epilogue (fp32-exact) ----
            const float K0v = par[0], K1v = par[1], L0v = par[2], L1v = par[3];
            const float Ms2v = par[5], K1L1v = par[6];
            {
                float K = fmaf(a0v, K1v, K0v);
                Ks0 = fmaf(K, Ms2v, Ks0);
                float tL = fmaf(a0v, L1v, L0v) - fabsf(l0);
                float BF = fmaf(a0v * a0v * nn0, K1L1v, K * tL);
                Bs0 = fmaf(BF, Msv, Bs0);
            }
            {
                float K = fmaf(a1v, K1v, K0v);
                Ks1 = fmaf(K, Ms2v, Ks1);
                float tL = fmaf(a1v, L1v, L0v) - fabsf(l1);
                float BF = fmaf(a1v * a1v * nn1, K1L1v, K * tL);
                Bs1 = fmaf(BF, Msv, Bs1);
            }
        }

        // ---- expm epilogue + stores (one lane per quad) ----
        if (tig == 0) {
            float o0, o1;
            finalize(Ks0, Bs0, ss0.x, ss0.y, Iv, invI, Bv, Kv, o0, o1);
            out[e0]  = o0;
            seg2[e0] = make_float2(o0, o1);
            finalize(Ks1, Bs1, ss1.x, ss1.y, Iv, invI, Bv, Kv, o0, o1);
            out[e1]  = o0;
            seg2[e1] = make_float2(o0, o1);
        }
    }
}

extern "C" void kernel_launch(void* const* d_in, const int* in_sizes, int n_in,
                              void* d_out, int out_size) {
    const float* SS  = (const float*)d_in[0];
    const float* AL  = (const float*)d_in[1];
    const float* K0  = (const float*)d_in[2];
    const float* K1  = (const float*)d_in[3];
    const float* L0  = (const float*)d_in[4];
    const float* L1  = (const float*)d_in[5];
    const float* Ms  = (const float*)d_in[6];
    const float* Ip  = (const float*)d_in[7];
    const float* Bv  = (const float*)d_in[8];
    const float* Kv  = (const float*)d_in[9];
    const float* W1  = (const float*)d_in[10];
    const float* b1  = (const float*)d_in[11];
    const float* W2  = (const float*)d_in[12];
    const float* b2  = (const float*)d_in[13];
    const float* W3  = (const float*)d_in[14];
    const float* b3  = (const float*)d_in[15];
    const float* W4  = (const float*)d_in[16];
    const float* b4  = (const float*)d_in[17];
    float* out = (float*)d_out;

    const int B = in_sizes[0] / 2;
    const int grid = (B + NT - 1) / NT;   // each warp: 2 chunks of 16 elements

    cudaFuncSetAttribute(joint_mma, cudaFuncAttributeMaxDynamicSharedMemorySize, SMEM_BYTES);
    joint_mma<<<grid, NT, SMEM_BYTES>>>(SS, AL, K0, K1, L0, L1, Ms, Ip, Bv, Kv,
                                        W1, b1, W2, b2, W3, b3, W4, b4, out, B);
}

// round 9
// speedup vs baseline: 2.7467x; 1.0691x over previous
#include <cuda_runtime.h>
#include <cuda_bf16.h>
#include <cstdint>
#include <cmath>

#define NT 448                 // 14 warps per CTA, grid=147, one wave
#define DTC 0.0166667f
#define NNR 0.3f

// ---- smem layout (u32 units) ----
#define WB_O   0               // bf16x2 weight frags: ((((m*3+l)*2+ks)*2+kh)*32+o)*4+tig
#define BS_O   12288           // fp32 [m][3][32] biases b1,b2,b3
#define W4_O   13056           // fp32 [m][32]
#define B4_O   13312           // fp32 [8]
#define PAR_O  13320           // fp32 [8][8]
#define SMEM_U 13384
#define SMEM_BYTES (SMEM_U*4)

__device__ __forceinline__ int widx(int m, int l, int ks, int kh, int o, int tig) {
    return ((((m * 3 + l) * 2 + ks) * 2 + kh) * 32 + o) * 4 + tig;
}

#define CVT_BF16X2(res, a, b) \
    asm("cvt.rn.bf16x2.f32 %0, %1, %2;" : "=r"(res) : "f"(b), "f"(a))

__device__ __forceinline__ void mma16816(float* d, const uint32_t* a, uint32_t b0, uint32_t b1) {
    asm volatile("mma.sync.aligned.m16n8k16.row.col.f32.bf16.bf16.f32 "
                 "{%0,%1,%2,%3}, {%4,%5,%6,%7}, {%8,%9}, {%0,%1,%2,%3};"
                 : "+f"(d[0]), "+f"(d[1]), "+f"(d[2]), "+f"(d[3])
                 : "r"(a[0]), "r"(a[1]), "r"(a[2]), "r"(a[3]), "r"(b0), "r"(b1));
}

__device__ __forceinline__ float tanh_ap(float x) {
    float y; asm("tanh.approx.f32 %0, %1;" : "=f"(y) : "f"(x)); return y;
}
__device__ __forceinline__ float leakys(float x) {
    return fmaf(0.505f, x, 0.495f * fabsf(x));
}

// closed-form 2x2 expm + phi1 solve (validated R1-R8)
__device__ __forceinline__ void finalize(float Ks, float Bs, float s0, float s1,
                                         float Iv, float invI, float Bv, float Kv,
                                         float& o0, float& o1) {
    float A10 = -(Ks + Kv) * invI;
    float Dd  = 2.0f * sqrtf(fmaxf(Ks * Iv, 0.0f));
    float A11 = -(Dd + Bv) * invI;
    float B10 = Bs * invI;
    float a10 = A10 * DTC, a11 = A11 * DTC;
    float s = 0.5f * a11;
    float q = fmaf(s, s, DTC * a10);
    float c, kf;
    if (q >= 0.0f) {
        float w = sqrtf(q);
        c = coshf(w);
        kf = (w > 1e-4f) ? sinhf(w) / w : 1.0f + q * (1.0f / 6.0f);
    } else {
        float w = sqrtf(-q);
        c = __cosf(w);
        kf = (w > 1e-4f) ? __sinf(w) / w : 1.0f + q * (1.0f / 6.0f);
    }
    float es = __expf(s);
    float g  = es * fmaf(-s, kf, c);
    float kk = es * kf;
    float Ad01 = kk * DTC;
    float Ad10 = kk * a10;
    float Ad11 = g + kk * a11;
    float v  = DTC * B10;
    float y1 = kk * v;
    float r1 = (Ad11 - 1.0f) * v;
    float y0 = (r1 - a11 * y1) / a10;
    o0 = fmaf(g,    s0, fmaf(Ad01, s1, y0));
    o1 = fmaf(Ad10, s0, fmaf(Ad11, s1, y1));
}

__global__ __launch_bounds__(NT, 1)
void joint_mma(const float* __restrict__ SS,  const float* __restrict__ AL,
               const float* __restrict__ K0,  const float* __restrict__ K1,
               const float* __restrict__ L0,  const float* __restrict__ L1,
               const float* __restrict__ Ms,  const float* __restrict__ Ip,
               const float* __restrict__ Bvp, const float* __restrict__ Kvp,
               const float* __restrict__ W1,  const float* __restrict__ b1,
               const float* __restrict__ W2,  const float* __restrict__ b2,
               const float* __restrict__ W3,  const float* __restrict__ b3,
               const float* __restrict__ W4,  const float* __restrict__ b4,
               float* __restrict__ out, int B) {
    extern __shared__ uint32_t smu[];
    float* smf = reinterpret_cast<float*>(smu);
    const int tid = threadIdx.x;

    // ---- stage weight fragments (bf16x2, mma B-fragment order) ----
    for (int t = tid; t < 12288; t += NT) {
        int m  = t / 1536;  int r = t - m * 1536;
        int l  = r / 512;   r -= l * 512;
        int ks = r / 256;   r -= ks * 256;
        int kh = r / 128;   r -= kh * 128;
        int o  = r >> 2;    int tg = r & 3;
        int i0 = ks * 16 + kh * 8 + tg * 2;
        float v0 = 0.0f, v1 = 0.0f;
        if (l == 0) {
            if (i0 < 3)     v0 = W1[(m * 32 + o) * 3 + i0];
            if (i0 + 1 < 3) v1 = W1[(m * 32 + o) * 3 + i0 + 1];
        } else {
            const float* W = (l == 1) ? W2 : W3;
            v0 = W[(m * 32 + o) * 32 + i0];
            v1 = W[(m * 32 + o) * 32 + i0 + 1];
        }
        uint32_t pk; CVT_BF16X2(pk, v0, v1);
        smu[WB_O + t] = pk;
    }
    for (int t = tid; t < 768; t += NT) {
        int m = t / 96, r = t - m * 96, li = r / 32, o = r & 31;
        const float* bp = (li == 0) ? b1 : (li == 1) ? b2 : b3;
        smf[BS_O + t] = bp[m * 32 + o];
    }
    for (int t = tid; t < 256; t += NT) smf[W4_O + t] = W4[t];
    if (tid < 8) {
        smf[B4_O + tid] = b4[tid];
        float ms = Ms[tid];
        float* p = smf + PAR_O + tid * 8;
        p[0] = K0[tid]; p[1] = K1[tid]; p[2] = L0[tid]; p[3] = L1[tid];
        p[4] = ms; p[5] = ms * ms; p[6] = K1[tid] * L1[tid];
    }
    __syncthreads();

    const int lane = tid & 31, wid = tid >> 5;
    const int g = lane >> 2, tig = lane & 3;
    const int cb = 2 * tig;
    const float Iv = __ldg(Ip), Bv = __ldg(Bvp), Kv = __ldg(Kvp);
    const float invI = 1.0f / Iv;
    const float2* SS2 = reinterpret_cast<const float2*>(SS);
    float2* seg2 = reinterpret_cast<float2*>(out + B);

    // two chunks of 16 elements per warp, processed interleaved
    const int chunk0 = (blockIdx.x * 14 + wid) * 2;
    int e[4];                               // {c0:row g, c0:row g+8, c1:row g, c1:row g+8}
    e[0] = chunk0 * 16 + g;
    e[1] = chunk0 * 16 + g + 8;
    e[2] = chunk0 * 16 + 16 + g;
    e[3] = chunk0 * 16 + 16 + g + 8;
#pragma unroll
    for (int q = 0; q < 4; q++) if (e[q] >= B) e[q] = B - 1;

    float2 ss[4];
#pragma unroll
    for (int q = 0; q < 4; q++) ss[q] = SS2[e[q]];
    float Ks[4] = {0.f, 0.f, 0.f, 0.f};
    float Bs[4] = {0.f, 0.f, 0.f, 0.f};

#pragma unroll 1
    for (int m = 0; m < 8; m++) {
        const float* par = smf + PAR_O + m * 8;
        const float Msv = par[4];
        float a[4], lv[4];
#pragma unroll
        for (int q = 0; q < 4; q++) {
            a[q]  = fminf(fmaxf(__ldg(&AL[(size_t)e[q] * 8 + m]), 0.0f), 1.0f);
            lv[q] = ss[q].x * Msv;
        }

        // ---- layer-1 A fragments (x = [l, dl, a, 0...], K=16 padded) ----
        float D[2][4][4];
        {
            uint32_t A0[2][4];
#pragma unroll
            for (int ch = 0; ch < 2; ch++) {
                uint32_t r0 = 0, r1 = 0;
                if (tig == 0) {
                    CVT_BF16X2(r0, lv[ch*2],   ss[ch*2].y   * Msv);
                    CVT_BF16X2(r1, lv[ch*2+1], ss[ch*2+1].y * Msv);
                } else if (tig == 1) {
                    CVT_BF16X2(r0, a[ch*2],   0.0f);
                    CVT_BF16X2(r1, a[ch*2+1], 0.0f);
                }
                A0[ch][0] = r0; A0[ch][1] = r1; A0[ch][2] = 0u; A0[ch][3] = 0u;
            }
#pragma unroll
            for (int t4 = 0; t4 < 4; t4++) {
                uint32_t bb0 = smu[WB_O + widx(m, 0, 0, 0, t4 * 8 + g, tig)];
                uint32_t bb1 = smu[WB_O + widx(m, 0, 0, 1, t4 * 8 + g, tig)];
#pragma unroll
                for (int ch = 0; ch < 2; ch++) {
#pragma unroll
                    for (int i = 0; i < 4; i++) D[ch][t4][i] = 0.0f;
                    mma16816(D[ch][t4], A0[ch], bb0, bb1);
                }
            }
        }

        // ---- layers 2,3: bias+leaky -> A frags -> 2-step K=32 mma ----
#pragma unroll 1
        for (int l = 1; l <= 2; l++) {
            uint32_t Ak0[2][4], Ak1[2][4];
            const float* bb = smf + BS_O + (m * 3 + (l - 1)) * 32 + cb;
#pragma unroll
            for (int t4 = 0; t4 < 4; t4++) {
                float2 bp = *reinterpret_cast<const float2*>(bb + t4 * 8);
#pragma unroll
                for (int ch = 0; ch < 2; ch++) {
                    float h0 = leakys(D[ch][t4][0] + bp.x);
                    float h1 = leakys(D[ch][t4][1] + bp.y);
                    float h2 = leakys(D[ch][t4][2] + bp.x);
                    float h3 = leakys(D[ch][t4][3] + bp.y);
                    uint32_t r01, r23;
                    CVT_BF16X2(r01, h0, h1);
                    CVT_BF16X2(r23, h2, h3);
                    if      (t4 == 0) { Ak0[ch][0] = r01; Ak0[ch][1] = r23; }
                    else if (t4 == 1) { Ak0[ch][2] = r01; Ak0[ch][3] = r23; }
                    else if (t4 == 2) { Ak1[ch][0] = r01; Ak1[ch][1] = r23; }
                    else              { Ak1[ch][2] = r01; Ak1[ch][3] = r23; }
                }
            }
#pragma unroll
            for (int t4 = 0; t4 < 4; t4++) {
                uint32_t b00 = smu[WB_O + widx(m, l, 0, 0, t4 * 8 + g, tig)];
                uint32_t b01 = smu[WB_O + widx(m, l, 0, 1, t4 * 8 + g, tig)];
                uint32_t b10 = smu[WB_O + widx(m, l, 1, 0, t4 * 8 + g, tig)];
                uint32_t b11 = smu[WB_O + widx(m, l, 1, 1, t4 * 8 + g, tig)];
#pragma unroll
                for (int ch = 0; ch < 2; ch++) {
#pragma unroll
                    for (int i = 0; i < 4; i++) D[ch][t4][i] = 0.0f;
                    mma16816(D[ch][t4], Ak0[ch], b00, b01);
                    mma16816(D[ch][t4], Ak1[ch], b10, b11);
                }
            }
        }

        // ---- layer 4 (32->1): quad-local dot + quad reduce ----
        float s[4] = {0.f, 0.f, 0.f, 0.f};
        {
            const float* bb = smf + BS_O + (m * 3 + 2) * 32 + cb;
            const float* w4 = smf + W4_O + m * 32 + cb;
#pragma unroll
            for (int t4 = 0; t4 < 4; t4++) {
                float2 bp = *reinterpret_cast<const float2*>(bb + t4 * 8);
                float2 wp = *reinterpret_cast<const float2*>(w4 + t4 * 8);
#pragma unroll
                for (int ch = 0; ch < 2; ch++) {
                    s[ch*2]   = fmaf(leakys(D[ch][t4][0] + bp.x), wp.x, s[ch*2]);
                    s[ch*2]   = fmaf(leakys(D[ch][t4][1] + bp.y), wp.y, s[ch*2]);
                    s[ch*2+1] = fmaf(leakys(D[ch][t4][2] + bp.x), wp.x, s[ch*2+1]);
                    s[ch*2+1] = fmaf(leakys(D[ch][t4][3] + bp.y), wp.y, s[ch*2+1]);
                }
            }
#pragma unroll
            for (int q = 0; q < 4; q++) {
                s[q] += __shfl_xor_sync(0xffffffffu, s[q], 1);
                s[q] += __shfl_xor_sync(0xffffffffu, s[q], 2);
            }
        }
        const float b4v = smf[B4_O + m];
        const float K0v = par[0], K1v = par[1], L0v = par[2], L1v = par[3];
        const float Ms2v = par[5], K1L1v = par[6];
#pragma unroll
        for (int q = 0; q < 4; q++) {
            float nn = NNR * tanh_ap(s[q] + b4v);
            float K = fmaf(a[q], K1v, K0v);
            Ks[q] = fmaf(K, Ms2v, Ks[q]);
            float tL = fmaf(a[q], L1v, L0v) - fabsf(lv[q]);
            float BF = fmaf(a[q] * a[q] * nn, K1L1v, K * tL);
            Bs[q] = fmaf(BF, Msv, Bs[q]);
        }
    }

    // ---- expm epilogue + stores (one lane per quad) ----
    if (tig == 0) {
#pragma unroll
        for (int q = 0; q < 4; q++) {
            float o0, o1;
            finalize(Ks[q], Bs[q], ss[q].x, ss[q].y, Iv, invI, Bv, Kv, o0, o1);
            out[e[q]]  = o0;
            seg2[e[q]] = make_float2(o0, o1);
        }
    }
}

extern "C" void kernel_launch(void* const* d_in, const int* in_sizes, int n_in,
                              void* d_out, int out_size) {
    const float* SS  = (const float*)d_in[0];
    const float* AL  = (const float*)d_in[1];
    const float* K0  = (const float*)d_in[2];
    const float* K1  = (const float*)d_in[3];
    const float* L0  = (const float*)d_in[4];
    const float* L1  = (const float*)d_in[5];
    const float* Ms  = (const float*)d_in[6];
    const float* Ip  = (const float*)d_in[7];
    const float* Bv  = (const float*)d_in[8];
    const float* Kv  = (const float*)d_in[9];
    const float* W1  = (const float*)d_in[10];
    const float* b1  = (const float*)d_in[11];
    const float* W2  = (const float*)d_in[12];
    const float* b2  = (const float*)d_in[13];
    const float* W3  = (const float*)d_in[14];
    const float* b3  = (const float*)d_in[15];
    const float* W4  = (const float*)d_in[16];
    const float* b4  = (const float*)d_in[17];
    float* out = (float*)d_out;

    const int B = in_sizes[0] / 2;
    const int perCTA = NT;                  // 14 warps * 32 elements
    const int grid = (B + perCTA - 1) / perCTA;

    cudaFuncSetAttribute(joint_mma, cudaFuncAttributeMaxDynamicSharedMemorySize, SMEM_BYTES);
    joint_mma<<<grid, NT, SMEM_BYTES>>>(SS, AL, K0, K1, L0, L1, Ms, Ip, Bv, Kv,
                                        W1, b1, W2, b2, W3, b3, W4, b4, out, B);
}